// round 4
// baseline (speedup 1.0000x reference)
#include <cuda_runtime.h>
#include <cstdint>
#include <math.h>

// Problem constants
#define MROWS 10000
#define HID   64
#define KSPL  5          // K-split for the big GEMM (10000/5 = 2000 = 125 * BK)

// GEMM tiling
#define BM 128
#define BN 64
#define BK 16
#define KPAD 20          // A smem row stride (floats): conflict-free a-frag reads
#define NPAD 72          // B smem row stride (floats): conflict-free b-frag reads

// Scratch (static device globals: no allocation anywhere)
__device__ float g_xw[2 * MROWS * HID];                 // x@W1, x@W2
__device__ float g_part[2 * KSPL * MROWS * HID];        // K-split partials of adj@xw
__device__ float g_emb[MROWS * HID];                    // fallback emb target

__device__ __forceinline__ uint32_t f2tf(float x) {
    uint32_t u;
    asm("cvt.rna.tf32.f32 %0, %1;" : "=r"(u) : "f"(x));
    return u;
}

__device__ __forceinline__ void mma8(float& c0, float& c1, float& c2, float& c3,
                                     uint32_t a0, uint32_t a1, uint32_t a2, uint32_t a3,
                                     uint32_t b0, uint32_t b1) {
    asm("mma.sync.aligned.m16n8k8.row.col.f32.tf32.tf32.f32 "
        "{%0,%1,%2,%3}, {%4,%5,%6,%7}, {%8,%9}, {%0,%1,%2,%3};"
        : "+f"(c0), "+f"(c1), "+f"(c2), "+f"(c3)
        : "r"(a0), "r"(a1), "r"(a2), "r"(a3), "r"(b0), "r"(b1));
}

// C[(by*gridDim.z + bz)*M*64 + m*64 + n] = A_by[m, kBase:kBase+kChunk] @ B_by[kBase:..., :64]
// A row-major with row stride lda. B row-major [K,64]. Guards on M only
// (kChunk must be a multiple of BK and in-range — guaranteed by launch params).
__global__ __launch_bounds__(256, 2)
void gemm_tf32_kernel(const float* __restrict__ A0, const float* __restrict__ A1,
                      const float* __restrict__ B0, const float* __restrict__ B1,
                      float* __restrict__ Cbase, int M, int lda, int kChunk)
{
    __shared__ __align__(16) uint32_t As[2][BM * KPAD];
    __shared__ __align__(16) uint32_t Bs[2][BK * NPAD];

    const int tid  = threadIdx.x;
    const float* A = blockIdx.y ? A1 : A0;
    const float* B = blockIdx.y ? B1 : B0;
    float* C = Cbase + (size_t)(blockIdx.y * gridDim.z + blockIdx.z) * ((size_t)M * BN);

    const int m0     = blockIdx.x * BM;
    const int kBase  = blockIdx.z * kChunk;
    const int ktiles = kChunk / BK;

    const int lane = tid & 31;
    const int warp = tid >> 5;
    const int wm0  = (warp & 3) * 32;   // warp grid 4(m) x 2(n); warp tile 32x32
    const int wn0  = (warp >> 2) * 32;
    const int r    = lane >> 2;         // 0..7
    const int c    = lane & 3;          // 0..3

    // global->smem staging mapping
    const int arow = tid >> 2;          // 0..63 (and +64)
    const int acol = (tid & 3) * 4;     // 0,4,8,12
    const int brow = tid >> 4;          // 0..15
    const int bcol = (tid & 15) * 4;    // 0..60

    const int  ar0 = m0 + arow;
    const int  ar1 = ar0 + 64;
    const bool v0  = ar0 < M;
    const bool v1  = ar1 < M;

    const float4* Ap0 = (const float4*)(A + (size_t)ar0 * lda + kBase + acol);
    const float4* Ap1 = (const float4*)(A + (size_t)ar1 * lda + kBase + acol);
    const float4* Bp  = (const float4*)(B + (size_t)(kBase + brow) * BN + bcol);

    float acc[2][4][4];
#pragma unroll
    for (int a = 0; a < 2; ++a)
#pragma unroll
        for (int b = 0; b < 4; ++b)
#pragma unroll
            for (int d = 0; d < 4; ++d) acc[a][b][d] = 0.f;

    const float4 Z4 = make_float4(0.f, 0.f, 0.f, 0.f);
    float4 pa0, pa1, pb;

    // prologue: tile 0
    pa0 = v0 ? Ap0[0] : Z4;
    pa1 = v1 ? Ap1[0] : Z4;
    pb  = Bp[0];
    *(uint4*)&As[0][arow * KPAD + acol] =
        make_uint4(f2tf(pa0.x), f2tf(pa0.y), f2tf(pa0.z), f2tf(pa0.w));
    *(uint4*)&As[0][(arow + 64) * KPAD + acol] =
        make_uint4(f2tf(pa1.x), f2tf(pa1.y), f2tf(pa1.z), f2tf(pa1.w));
    *(uint4*)&Bs[0][brow * NPAD + bcol] =
        make_uint4(f2tf(pb.x), f2tf(pb.y), f2tf(pb.z), f2tf(pb.w));
    __syncthreads();

    for (int t = 0; t < ktiles; ++t) {
        const int cur = t & 1;

        if (t + 1 < ktiles) {           // prefetch next tile (global -> regs)
            const int tt = t + 1;
            pa0 = v0 ? Ap0[tt * 4] : Z4;        // +BK floats = +4 float4 along k
            pa1 = v1 ? Ap1[tt * 4] : Z4;
            pb  = Bp[tt * 256];                 // +BK rows * 64 floats = +256 float4
        }

        const uint32_t* Ab = As[cur];
        const uint32_t* Bb = Bs[cur];
#pragma unroll
        for (int ks = 0; ks < 2; ++ks) {
            const int k8 = ks * 8;
            uint32_t af[2][4], bf[4][2];
#pragma unroll
            for (int mt = 0; mt < 2; ++mt) {
                const int row = wm0 + mt * 16 + r;
                af[mt][0] = Ab[row       * KPAD + k8 + c];
                af[mt][1] = Ab[(row + 8) * KPAD + k8 + c];
                af[mt][2] = Ab[row       * KPAD + k8 + c + 4];
                af[mt][3] = Ab[(row + 8) * KPAD + k8 + c + 4];
            }
#pragma unroll
            for (int nt = 0; nt < 4; ++nt) {
                const int col = wn0 + nt * 8 + r;
                bf[nt][0] = Bb[(k8 + c)     * NPAD + col];
                bf[nt][1] = Bb[(k8 + c + 4) * NPAD + col];
            }
#pragma unroll
            for (int mt = 0; mt < 2; ++mt)
#pragma unroll
                for (int nt = 0; nt < 4; ++nt)
                    mma8(acc[mt][nt][0], acc[mt][nt][1], acc[mt][nt][2], acc[mt][nt][3],
                         af[mt][0], af[mt][1], af[mt][2], af[mt][3],
                         bf[nt][0], bf[nt][1]);
        }

        if (t + 1 < ktiles) {           // regs -> other smem buffer
            const int nxt = (t + 1) & 1;
            *(uint4*)&As[nxt][arow * KPAD + acol] =
                make_uint4(f2tf(pa0.x), f2tf(pa0.y), f2tf(pa0.z), f2tf(pa0.w));
            *(uint4*)&As[nxt][(arow + 64) * KPAD + acol] =
                make_uint4(f2tf(pa1.x), f2tf(pa1.y), f2tf(pa1.z), f2tf(pa1.w));
            *(uint4*)&Bs[nxt][brow * NPAD + bcol] =
                make_uint4(f2tf(pb.x), f2tf(pb.y), f2tf(pb.z), f2tf(pb.w));
        }
        __syncthreads();
    }

    // epilogue: c0,c1 -> (row=r, cols 2c,2c+1); c2,c3 -> (row=r+8)
#pragma unroll
    for (int mt = 0; mt < 2; ++mt) {
        const int rowA = m0 + wm0 + mt * 16 + r;
        const int rowB = rowA + 8;
#pragma unroll
        for (int nt = 0; nt < 4; ++nt) {
            const int col = wn0 + nt * 8 + 2 * c;
            if (rowA < M)
                *(float2*)(C + (size_t)rowA * BN + col) =
                    make_float2(acc[mt][nt][0], acc[mt][nt][1]);
            if (rowB < M)
                *(float2*)(C + (size_t)rowB * BN + col) =
                    make_float2(acc[mt][nt][2], acc[mt][nt][3]);
        }
    }
}

// One warp per node row: reduce K-split partials + bias, 2-view attention
// softmax fuse, DEC soft assignment q.
__global__ void fuse_kernel(const float* __restrict__ part,
                            const float* __restrict__ b1, const float* __restrict__ b2,
                            const float* __restrict__ attnw, const float* __restrict__ clus,
                            float* __restrict__ emb_out, float* __restrict__ q_out, int M)
{
    const int warp = threadIdx.x >> 5;
    const int lane = threadIdx.x & 31;
    const int i = blockIdx.x * 8 + warp;
    if (i >= M) return;

    const int h0 = lane, h1 = lane + 32;
    const size_t M64 = (size_t)M * HID;

    float e1a = b1[h0], e1b = b1[h1];
    float e2a = b2[h0], e2b = b2[h1];
    const float* p1 = part + (size_t)i * HID;
    const float* p2 = part + (size_t)KSPL * M64 + (size_t)i * HID;
#pragma unroll
    for (int z = 0; z < KSPL; ++z) {
        e1a += p1[(size_t)z * M64 + h0];
        e1b += p1[(size_t)z * M64 + h1];
        e2a += p2[(size_t)z * M64 + h0];
        e2b += p2[(size_t)z * M64 + h1];
    }

    const float aw0 = attnw[h0], aw1 = attnw[h1];
    float w1 = e1a * aw0 + e1b * aw1;
    float w2 = e2a * aw0 + e2b * aw1;
#pragma unroll
    for (int o = 16; o; o >>= 1) {
        w1 += __shfl_xor_sync(0xffffffffu, w1, o);
        w2 += __shfl_xor_sync(0xffffffffu, w2, o);
    }
    const float mx  = fmaxf(w1, w2);
    const float x1  = expf(w1 - mx);
    const float x2  = expf(w2 - mx);
    const float inv = 1.f / (x1 + x2);
    const float be1 = x1 * inv, be2 = x2 * inv;

    const float ea = be1 * e1a + be2 * e2a;
    const float eb = be1 * e1b + be2 * e2b;
    emb_out[(size_t)i * HID + h0] = ea;
    emb_out[(size_t)i * HID + h1] = eb;

    if (!q_out) return;

    float tq[10];
    float s = 0.f;
#pragma unroll
    for (int k = 0; k < 10; ++k) {
        const float da = ea - clus[k * HID + h0];
        const float db = eb - clus[k * HID + h1];
        float d2 = da * da + db * db;
#pragma unroll
        for (int o = 16; o; o >>= 1) d2 += __shfl_xor_sync(0xffffffffu, d2, o);
        // q = (1/(1+d2/0.2))^0.6 ^1.2 (/2 cancels under row normalization)
        float tk = 1.f / (1.f + d2 * 5.0f);
        tk = powf(tk, 0.72f);
        tq[k] = tk;
        s += tk;
    }
    if (lane < 10) q_out[(size_t)i * 10 + lane] = tq[lane] / s;
}

extern "C" void kernel_launch(void* const* d_in, const int* in_sizes, int n_in,
                              void* d_out, int out_size)
{
    const float* x    = (const float*)d_in[0];
    const float* adj1 = (const float*)d_in[1];
    const float* adj2 = (const float*)d_in[2];
    const float* W1   = (const float*)d_in[3];
    const float* b1   = (const float*)d_in[4];
    const float* W2   = (const float*)d_in[5];
    const float* b2   = (const float*)d_in[6];
    const float* attn = (const float*)d_in[7];
    const float* clus = (const float*)d_in[8];

    float *xw, *part, *embS;
    cudaGetSymbolAddress((void**)&xw,   g_xw);
    cudaGetSymbolAddress((void**)&part, g_part);
    cudaGetSymbolAddress((void**)&embS, g_emb);

    const int mtiles = (MROWS + BM - 1) / BM;   // 79

    // GEMM1: xw_b = x @ W_b    (K=512, no split)
    dim3 g1(mtiles, 2, 1);
    gemm_tf32_kernel<<<g1, 256>>>(x, x, W1, W2, xw, MROWS, 512, 512);

    // GEMM2: partials of adj_b @ xw_b   (K=10000 split 5-ways)
    dim3 g2(mtiles, 2, KSPL);
    gemm_tf32_kernel<<<g2, 256>>>(adj1, adj2, xw, xw + MROWS * HID, part,
                                  MROWS, MROWS, MROWS / KSPL);

    // Fuse: reduce partials + bias, attention softmax, emb, q
    float* out = (float*)d_out;
    float* emb_out;
    float* q_out;
    const int embN = MROWS * HID;        // 640000
    const int qN   = MROWS * 10;         // 100000
    if (out_size >= embN + qN)      { emb_out = out;  q_out = out + embN; }
    else if (out_size >= embN)      { emb_out = out;  q_out = nullptr;    }
    else                            { emb_out = embS; q_out = out;        }

    fuse_kernel<<<(MROWS + 7) / 8, 256>>>(part, b1, b2, attn, clus, emb_out, q_out, MROWS);
}

// round 6
// speedup vs baseline: 1.5114x; 1.5114x over previous
#include <cuda_runtime.h>
#include <cstdint>
#include <math.h>

// Problem constants
#define MROWS 10000
#define HID   64
#define KSPL  5          // K-split for the big GEMM (10000/5 = 2000 = 125 * BK)

// GEMM tiling
#define BM 128
#define BN 64
#define BK 16
#define KPAD 20          // A smem row stride (floats): conflict-free a-frag reads
#define NPAD 72          // B smem row stride (floats): conflict-free b-frag reads

#define STAGES 5
#define WAIT_N 3         // STAGES-2: oldest outstanding group complete
#define AS_SZ (BM * KPAD)        // 2560 floats
#define BS_SZ (BK * NPAD)        // 1152 floats
#define STAGE_FLTS (AS_SZ + BS_SZ)               // 3712
#define SMEM_BYTES (STAGES * STAGE_FLTS * 4)     // 74240

// Scratch (static device globals: no allocation anywhere)
__device__ __align__(16) float g_xw[2 * MROWS * HID];          // x@W1, x@W2
__device__ __align__(16) float g_part[2 * KSPL * MROWS * HID]; // K-split partials
__device__ __align__(16) float g_emb[MROWS * HID];             // fallback emb target

__device__ __forceinline__ uint32_t f2tf(float x) {
    uint32_t u;
    asm("cvt.rna.tf32.f32 %0, %1;" : "=r"(u) : "f"(x));
    return u;
}

__device__ __forceinline__ void cp16(uint32_t dst, const void* src, bool v) {
    const int sz = v ? 16 : 0;   // src-size 0 => zero-fill, no gmem access
    asm volatile("cp.async.cg.shared.global [%0], [%1], 16, %2;\n"
                 :: "r"(dst), "l"(src), "r"(sz));
}

__device__ __forceinline__ void cp_commit() {
    asm volatile("cp.async.commit_group;\n");
}

__device__ __forceinline__ void cp_wait() {
    asm volatile("cp.async.wait_group %0;\n" :: "n"(WAIT_N));
}

__device__ __forceinline__ void mma8(float& c0, float& c1, float& c2, float& c3,
                                     uint32_t a0, uint32_t a1, uint32_t a2, uint32_t a3,
                                     uint32_t b0, uint32_t b1) {
    asm("mma.sync.aligned.m16n8k8.row.col.f32.tf32.tf32.f32 "
        "{%0,%1,%2,%3}, {%4,%5,%6,%7}, {%8,%9}, {%0,%1,%2,%3};"
        : "+f"(c0), "+f"(c1), "+f"(c2), "+f"(c3)
        : "r"(a0), "r"(a1), "r"(a2), "r"(a3), "r"(b0), "r"(b1));
}

// C[(by*gridDim.z + bz)*M*64 + m*64 + n] = A_by[m, kBase:kBase+kChunk] @ B_by[kBase:..., :64]
// A row-major (row stride lda), B row-major [K,64]. kChunk % BK == 0 guaranteed.
// 5-stage cp.async pipeline; tf32 round-to-nearest at fragment load.
__global__ __launch_bounds__(256, 2)
void gemm_tf32_kernel(const float* __restrict__ A0, const float* __restrict__ A1,
                      const float* __restrict__ B0, const float* __restrict__ B1,
                      float* __restrict__ Cbase, int M, int lda, int kChunk)
{
    extern __shared__ __align__(16) float dsmem[];

    const int tid  = threadIdx.x;
    const float* A = blockIdx.y ? A1 : A0;
    const float* B = blockIdx.y ? B1 : B0;
    float* C = Cbase + (size_t)(blockIdx.y * gridDim.z + blockIdx.z) * ((size_t)M * BN);

    const int m0     = blockIdx.x * BM;
    const int kBase  = blockIdx.z * kChunk;
    const int ktiles = kChunk / BK;

    const int lane = tid & 31;
    const int warp = tid >> 5;
    const int wm0  = (warp & 3) * 32;   // warp grid 4(m) x 2(n); warp tile 32x32
    const int wn0  = (warp >> 2) * 32;
    const int r    = lane >> 2;         // 0..7
    const int c    = lane & 3;          // 0..3

    // global->smem staging mapping (16B chunks)
    const int arow = tid >> 2;          // 0..63 (and +64)
    const int acol = (tid & 3) * 4;     // 0,4,8,12
    const int brow = tid >> 4;          // 0..15
    const int bcol = (tid & 15) * 4;    // 0..60

    const int  ar0 = m0 + arow;
    const int  ar1 = ar0 + 64;
    const bool v0  = ar0 < M;
    const bool v1  = ar1 < M;

    // global src pointers (clamped rows when invalid; src-size=0 prevents access)
    const float* gA0 = A + (size_t)(v0 ? ar0 : 0) * lda + kBase + acol;
    const float* gA1 = A + (size_t)(v1 ? ar1 : 0) * lda + kBase + acol;
    const float* gB  = B + (size_t)(kBase + brow) * BN + bcol;

    // smem dst (per-thread, per-stage)
    const uint32_t sBase = (uint32_t)__cvta_generic_to_shared(dsmem);
    const uint32_t dA0   = sBase + (arow * KPAD + acol) * 4;
    const uint32_t dA1   = sBase + ((arow + 64) * KPAD + acol) * 4;
    const uint32_t dB    = sBase + (AS_SZ + brow * NPAD + bcol) * 4;
    const uint32_t stgB  = STAGE_FLTS * 4;

    float acc[2][4][4];
#pragma unroll
    for (int a = 0; a < 2; ++a)
#pragma unroll
        for (int b = 0; b < 4; ++b)
#pragma unroll
            for (int d = 0; d < 4; ++d) acc[a][b][d] = 0.f;

    // prologue: fill STAGES-1 stages
#pragma unroll
    for (int s = 0; s < STAGES - 1; ++s) {
        if (s < ktiles) {
            const uint32_t so = s * stgB;
            cp16(dA0 + so, gA0 + s * BK, v0);
            cp16(dA1 + so, gA1 + s * BK, v1);
            cp16(dB + so,  gB + (size_t)s * BK * BN, true);
        }
        cp_commit();
    }

    int rd = 0;                 // stage holding tile t
    int wr = STAGES - 1;        // stage for tile t+STAGES-1

    for (int t = 0; t < ktiles; ++t) {
        cp_wait();              // tile t resident
        __syncthreads();        // all threads past iteration t-1's compute

        // issue loads for tile t+STAGES-1 into stage wr (consumed at t-1, now free)
        {
            const int tt = t + STAGES - 1;
            if (tt < ktiles) {
                const uint32_t so = wr * stgB;
                cp16(dA0 + so, gA0 + tt * BK, v0);
                cp16(dA1 + so, gA1 + tt * BK, v1);
                cp16(dB + so,  gB + (size_t)tt * BK * BN, true);
            }
            cp_commit();
            if (++wr == STAGES) wr = 0;
        }

        const float* Ab = dsmem + rd * STAGE_FLTS;
        const float* Bb = Ab + AS_SZ;
        if (++rd == STAGES) rd = 0;

#pragma unroll
        for (int ks = 0; ks < 2; ++ks) {
            const int k8 = ks * 8;
            uint32_t af[2][4], bf[4][2];
#pragma unroll
            for (int mt = 0; mt < 2; ++mt) {
                const int row = wm0 + mt * 16 + r;
                af[mt][0] = f2tf(Ab[row       * KPAD + k8 + c]);
                af[mt][1] = f2tf(Ab[(row + 8) * KPAD + k8 + c]);
                af[mt][2] = f2tf(Ab[row       * KPAD + k8 + c + 4]);
                af[mt][3] = f2tf(Ab[(row + 8) * KPAD + k8 + c + 4]);
            }
#pragma unroll
            for (int nt = 0; nt < 4; ++nt) {
                const int col = wn0 + nt * 8 + r;
                bf[nt][0] = f2tf(Bb[(k8 + c)     * NPAD + col]);
                bf[nt][1] = f2tf(Bb[(k8 + c + 4) * NPAD + col]);
            }
#pragma unroll
            for (int mt = 0; mt < 2; ++mt)
#pragma unroll
                for (int nt = 0; nt < 4; ++nt)
                    mma8(acc[mt][nt][0], acc[mt][nt][1], acc[mt][nt][2], acc[mt][nt][3],
                         af[mt][0], af[mt][1], af[mt][2], af[mt][3],
                         bf[nt][0], bf[nt][1]);
        }
    }

    // epilogue: c0,c1 -> (row=r, cols 2c,2c+1); c2,c3 -> (row=r+8)
#pragma unroll
    for (int mt = 0; mt < 2; ++mt) {
        const int rowA = m0 + wm0 + mt * 16 + r;
        const int rowB = rowA + 8;
#pragma unroll
        for (int nt = 0; nt < 4; ++nt) {
            const int col = wn0 + nt * 8 + 2 * c;
            if (rowA < M)
                *(float2*)(C + (size_t)rowA * BN + col) =
                    make_float2(acc[mt][nt][0], acc[mt][nt][1]);
            if (rowB < M)
                *(float2*)(C + (size_t)rowB * BN + col) =
                    make_float2(acc[mt][nt][2], acc[mt][nt][3]);
        }
    }
}

// One warp per node row: reduce K-split partials + bias, 2-view attention
// softmax fuse, DEC soft assignment q.
__global__ void fuse_kernel(const float* __restrict__ part,
                            const float* __restrict__ b1, const float* __restrict__ b2,
                            const float* __restrict__ attnw, const float* __restrict__ clus,
                            float* __restrict__ emb_out, float* __restrict__ q_out, int M)
{
    const int warp = threadIdx.x >> 5;
    const int lane = threadIdx.x & 31;
    const int i = blockIdx.x * 8 + warp;
    if (i >= M) return;

    const int h0 = lane, h1 = lane + 32;
    const size_t M64 = (size_t)M * HID;

    float e1a = b1[h0], e1b = b1[h1];
    float e2a = b2[h0], e2b = b2[h1];
    const float* p1 = part + (size_t)i * HID;
    const float* p2 = part + (size_t)KSPL * M64 + (size_t)i * HID;
#pragma unroll
    for (int z = 0; z < KSPL; ++z) {
        e1a += p1[(size_t)z * M64 + h0];
        e1b += p1[(size_t)z * M64 + h1];
        e2a += p2[(size_t)z * M64 + h0];
        e2b += p2[(size_t)z * M64 + h1];
    }

    const float aw0 = attnw[h0], aw1 = attnw[h1];
    float w1 = e1a * aw0 + e1b * aw1;
    float w2 = e2a * aw0 + e2b * aw1;
#pragma unroll
    for (int o = 16; o; o >>= 1) {
        w1 += __shfl_xor_sync(0xffffffffu, w1, o);
        w2 += __shfl_xor_sync(0xffffffffu, w2, o);
    }
    const float mx  = fmaxf(w1, w2);
    const float x1  = expf(w1 - mx);
    const float x2  = expf(w2 - mx);
    const float inv = 1.f / (x1 + x2);
    const float be1 = x1 * inv, be2 = x2 * inv;

    const float ea = be1 * e1a + be2 * e2a;
    const float eb = be1 * e1b + be2 * e2b;
    emb_out[(size_t)i * HID + h0] = ea;
    emb_out[(size_t)i * HID + h1] = eb;

    if (!q_out) return;

    float tq[10];
    float s = 0.f;
#pragma unroll
    for (int k = 0; k < 10; ++k) {
        const float da = ea - clus[k * HID + h0];
        const float db = eb - clus[k * HID + h1];
        float d2 = da * da + db * db;
#pragma unroll
        for (int o = 16; o; o >>= 1) d2 += __shfl_xor_sync(0xffffffffu, d2, o);
        // q = (1/(1+d2/0.2))^0.6 ^1.2 (/2 cancels under row normalization)
        float tk = 1.f / (1.f + d2 * 5.0f);
        tk = powf(tk, 0.72f);
        tq[k] = tk;
        s += tk;
    }
    if (lane < 10) q_out[(size_t)i * 10 + lane] = tq[lane] / s;
}

extern "C" void kernel_launch(void* const* d_in, const int* in_sizes, int n_in,
                              void* d_out, int out_size)
{
    const float* x    = (const float*)d_in[0];
    const float* adj1 = (const float*)d_in[1];
    const float* adj2 = (const float*)d_in[2];
    const float* W1   = (const float*)d_in[3];
    const float* b1   = (const float*)d_in[4];
    const float* W2   = (const float*)d_in[5];
    const float* b2   = (const float*)d_in[6];
    const float* attn = (const float*)d_in[7];
    const float* clus = (const float*)d_in[8];

    float *xw, *part, *embS;
    cudaGetSymbolAddress((void**)&xw,   g_xw);
    cudaGetSymbolAddress((void**)&part, g_part);
    cudaGetSymbolAddress((void**)&embS, g_emb);

    cudaFuncSetAttribute(gemm_tf32_kernel,
                         cudaFuncAttributeMaxDynamicSharedMemorySize, SMEM_BYTES);

    const int mtiles = (MROWS + BM - 1) / BM;   // 79

    // GEMM1: xw_b = x @ W_b    (K=512, no split)
    dim3 g1(mtiles, 2, 1);
    gemm_tf32_kernel<<<g1, 256, SMEM_BYTES>>>(x, x, W1, W2, xw, MROWS, 512, 512);

    // GEMM2: partials of adj_b @ xw_b   (K=10000 split 5-ways)
    dim3 g2(mtiles, 2, KSPL);
    gemm_tf32_kernel<<<g2, 256, SMEM_BYTES>>>(adj1, adj2, xw, xw + MROWS * HID, part,
                                              MROWS, MROWS, MROWS / KSPL);

    // Fuse: reduce partials + bias, attention softmax, emb, q
    float* out = (float*)d_out;
    float* emb_out;
    float* q_out;
    const int embN = MROWS * HID;        // 640000
    const int qN   = MROWS * 10;         // 100000
    if (out_size >= embN + qN)      { emb_out = out;  q_out = out + embN; }
    else if (out_size >= embN)      { emb_out = out;  q_out = nullptr;    }
    else                            { emb_out = embS; q_out = out;        }

    fuse_kernel<<<(MROWS + 7) / 8, 256>>>(part, b1, b2, attn, clus, emb_out, q_out, MROWS);
}